// round 5
// baseline (speedup 1.0000x reference)
#include <cuda_runtime.h>
#include <cuda_bf16.h>

// ---------------------------------------------------------------------------
// Problem constants (from reference)
// ---------------------------------------------------------------------------
#define N0 256000
#define N1 25600
#define N2 2560
#define N3 512
#define D_IN 1024
#define D_H 256
#define D_OUT 19
#define F0 10
#define F1 10
#define F2 5

// ---------------------------------------------------------------------------
// Scratch (static __device__ globals -> allocation-free, graph-capturable)
// ---------------------------------------------------------------------------
__device__ float g_neigh0[N1 * D_IN];   // 100 MB : mean-gathered x for layer 0
__device__ float g_h1[N1 * D_H];        //  25 MB : layer-0 output
__device__ float g_neigh1[N2 * D_H];
__device__ float g_h2[N2 * D_H];
__device__ float g_neigh2[N3 * D_H];

// ---------------------------------------------------------------------------
// Kernel 1: gather + mean over FANOUT neighbors. One block per dst row.
// ---------------------------------------------------------------------------
template <int FANOUT>
__global__ void gather_mean_kernel(const float* __restrict__ src,
                                   const int* __restrict__ nbr,
                                   float* __restrict__ dst,
                                   int d4) {
    const int i = blockIdx.x;
    const float4* __restrict__ s4 = reinterpret_cast<const float4*>(src);
    float4* __restrict__ d4p = reinterpret_cast<float4*>(dst);
    constexpr float inv = 1.0f / (float)FANOUT;

    const float4* base[FANOUT];
#pragma unroll
    for (int j = 0; j < FANOUT; ++j) {
        int n = __ldg(&nbr[i * FANOUT + j]);
        base[j] = s4 + (long)n * d4;
    }

    for (int c = threadIdx.x; c < d4; c += blockDim.x) {
        float acc_x = 0.f, acc_y = 0.f, acc_z = 0.f, acc_w = 0.f;
#pragma unroll
        for (int j = 0; j < FANOUT; ++j) {
            float4 v = __ldg(&base[j][c]);
            acc_x += v.x; acc_y += v.y; acc_z += v.z; acc_w += v.w;
        }
        d4p[(long)i * d4 + c] =
            make_float4(acc_x * inv, acc_y * inv, acc_z * inv, acc_w * inv);
    }
}

// ---------------------------------------------------------------------------
// Kernel 2: fused dual GEMM  C = act(Aself @ Ws + Aneigh @ Wn + b)
// BM=128, BN=64, BK=16, 256 threads, 8x4 register tile per thread.
// Software-pipelined double-buffered smem: LDG for tile t+1 issued before
// computing tile t; STS after. Hides L2/DRAM latency behind FFMA stream.
// ---------------------------------------------------------------------------
template <int K, bool RELU>
__global__ __launch_bounds__(256) void sage_gemm_kernel(
    const float* __restrict__ Aself, const float* __restrict__ Aneigh,
    const float* __restrict__ Ws, const float* __restrict__ Wn,
    const float* __restrict__ bias, float* __restrict__ C) {
    constexpr int BM = 128, BN = 64, BK = 16, N = 256;
    constexpr int TILES = K / BK;          // tiles per pass
    constexpr int TOTAL = 2 * TILES;       // both passes, flattened
    __shared__ float As[2][BK][BM + 4];    // +4 pad: row stride 528B
    __shared__ float Bs[2][BK][BN];

    const int tid = threadIdx.x;
    const int tx = tid & 15;               // 0..15 -> 4 output cols
    const int ty = tid >> 4;               // 0..15 -> 8 output rows
    const int m0 = blockIdx.y * BM;
    const int n0 = blockIdx.x * BN;

    // Per-thread load coordinates (fixed across tiles)
    const int am0 = (tid + 0)   >> 2;          // A row for load 0
    const int ak0 = ((tid + 0)  & 3) * 4;      // A k for load 0
    const int am1 = (tid + 256) >> 2;          // A row for load 1
    const int ak1 = ((tid + 256)& 3) * 4;
    const int bk  = tid >> 4;                  // B k row
    const int bn  = (tid & 15) * 4;            // B col

    float acc[8][4];
#pragma unroll
    for (int i = 0; i < 8; ++i)
#pragma unroll
        for (int j = 0; j < 4; ++j) acc[i][j] = 0.f;

    float4 pa0, pa1, pb;                   // prefetch registers

    // ---- prologue: load tile 0 (pass 0) ----
    {
        const float* __restrict__ A = Aself;
        const float* __restrict__ B = Ws;
        pa0 = *reinterpret_cast<const float4*>(&A[(long)(m0 + am0) * K + ak0]);
        pa1 = *reinterpret_cast<const float4*>(&A[(long)(m0 + am1) * K + ak1]);
        pb  = *reinterpret_cast<const float4*>(&B[(long)bk * N + n0 + bn]);
        As[0][ak0 + 0][am0] = pa0.x; As[0][ak0 + 1][am0] = pa0.y;
        As[0][ak0 + 2][am0] = pa0.z; As[0][ak0 + 3][am0] = pa0.w;
        As[0][ak1 + 0][am1] = pa1.x; As[0][ak1 + 1][am1] = pa1.y;
        As[0][ak1 + 2][am1] = pa1.z; As[0][ak1 + 3][am1] = pa1.w;
        *reinterpret_cast<float4*>(&Bs[0][bk][bn]) = pb;
    }
    __syncthreads();

#pragma unroll 1
    for (int t = 0; t < TOTAL; ++t) {
        const int cur = t & 1;
        const bool has_next = (t + 1 < TOTAL);

        // ---- issue LDGs for tile t+1 (overlaps with compute below) ----
        if (has_next) {
            const int tn = t + 1;
            const float* __restrict__ A = (tn < TILES) ? Aself : Aneigh;
            const float* __restrict__ B = (tn < TILES) ? Ws : Wn;
            const int k0 = (tn < TILES ? tn : tn - TILES) * BK;
            pa0 = *reinterpret_cast<const float4*>(&A[(long)(m0 + am0) * K + k0 + ak0]);
            pa1 = *reinterpret_cast<const float4*>(&A[(long)(m0 + am1) * K + k0 + ak1]);
            pb  = *reinterpret_cast<const float4*>(&B[(long)(k0 + bk) * N + n0 + bn]);
        }

        // ---- compute tile t from smem[cur] ----
#pragma unroll
        for (int kk = 0; kk < BK; ++kk) {
            float4 a0 = *reinterpret_cast<const float4*>(&As[cur][kk][ty * 8 + 0]);
            float4 a1 = *reinterpret_cast<const float4*>(&As[cur][kk][ty * 8 + 4]);
            float4 bv = *reinterpret_cast<const float4*>(&Bs[cur][kk][tx * 4]);
            float a[8] = {a0.x, a0.y, a0.z, a0.w, a1.x, a1.y, a1.z, a1.w};
            float b4[4] = {bv.x, bv.y, bv.z, bv.w};
#pragma unroll
            for (int i = 0; i < 8; ++i)
#pragma unroll
                for (int j = 0; j < 4; ++j) acc[i][j] += a[i] * b4[j];
        }

        // ---- store prefetched tile into the other buffer ----
        if (has_next) {
            const int nxt = cur ^ 1;
            As[nxt][ak0 + 0][am0] = pa0.x; As[nxt][ak0 + 1][am0] = pa0.y;
            As[nxt][ak0 + 2][am0] = pa0.z; As[nxt][ak0 + 3][am0] = pa0.w;
            As[nxt][ak1 + 0][am1] = pa1.x; As[nxt][ak1 + 1][am1] = pa1.y;
            As[nxt][ak1 + 2][am1] = pa1.z; As[nxt][ak1 + 3][am1] = pa1.w;
            *reinterpret_cast<float4*>(&Bs[nxt][bk][bn]) = pb;
        }
        __syncthreads();
    }

    // ---- epilogue: bias (+ ReLU), vectorized store ----
#pragma unroll
    for (int i = 0; i < 8; ++i) {
        int m = m0 + ty * 8 + i;
        int n = n0 + tx * 4;
        float4 v;
        v.x = acc[i][0] + bias[n + 0];
        v.y = acc[i][1] + bias[n + 1];
        v.z = acc[i][2] + bias[n + 2];
        v.w = acc[i][3] + bias[n + 3];
        if (RELU) {
            v.x = fmaxf(v.x, 0.f); v.y = fmaxf(v.y, 0.f);
            v.z = fmaxf(v.z, 0.f); v.w = fmaxf(v.w, 0.f);
        }
        *reinterpret_cast<float4*>(&C[(long)m * N + n]) = v;
    }
}

// ---------------------------------------------------------------------------
// Kernel 3: output layer (M=512, K=256, N=19). One block per row; one warp
// per output class, warp-shuffle reduction.
// ---------------------------------------------------------------------------
__global__ void sage_out_kernel(const float* __restrict__ h,
                                const float* __restrict__ hn,
                                const float* __restrict__ Ws,
                                const float* __restrict__ Wn,
                                const float* __restrict__ bias,
                                float* __restrict__ out) {
    const int i = blockIdx.x;
    const int w = threadIdx.x >> 5;
    const int lane = threadIdx.x & 31;
    __shared__ float sh[D_H], sn[D_H];
    for (int k = threadIdx.x; k < D_H; k += blockDim.x) {
        sh[k] = h[(long)i * D_H + k];
        sn[k] = hn[(long)i * D_H + k];
    }
    __syncthreads();
    if (w < D_OUT) {
        float acc = 0.f;
        for (int k = lane; k < D_H; k += 32)
            acc += sh[k] * Ws[k * D_OUT + w] + sn[k] * Wn[k * D_OUT + w];
#pragma unroll
        for (int o = 16; o; o >>= 1) acc += __shfl_xor_sync(0xffffffffu, acc, o);
        if (lane == 0) out[i * D_OUT + w] = acc + bias[w];
    }
}

// ---------------------------------------------------------------------------
// Launch
// ---------------------------------------------------------------------------
extern "C" void kernel_launch(void* const* d_in, const int* in_sizes, int n_in,
                              void* d_out, int out_size) {
    const float* x     = (const float*)d_in[0];
    const int*   nbr0  = (const int*)  d_in[1];
    const int*   nbr1  = (const int*)  d_in[2];
    const int*   nbr2  = (const int*)  d_in[3];
    const float* Ws0   = (const float*)d_in[4];
    const float* Wn0   = (const float*)d_in[5];
    const float* b0    = (const float*)d_in[6];
    const float* Ws1   = (const float*)d_in[7];
    const float* Wn1   = (const float*)d_in[8];
    const float* b1    = (const float*)d_in[9];
    const float* Ws2   = (const float*)d_in[10];
    const float* Wn2   = (const float*)d_in[11];
    const float* b2    = (const float*)d_in[12];
    float* out = (float*)d_out;

    float *p_neigh0, *p_h1, *p_neigh1, *p_h2, *p_neigh2;
    cudaGetSymbolAddress((void**)&p_neigh0, g_neigh0);
    cudaGetSymbolAddress((void**)&p_h1,     g_h1);
    cudaGetSymbolAddress((void**)&p_neigh1, g_neigh1);
    cudaGetSymbolAddress((void**)&p_h2,     g_h2);
    cudaGetSymbolAddress((void**)&p_neigh2, g_neigh2);

    // Layer 0
    gather_mean_kernel<F0><<<N1, 256>>>(x, nbr0, p_neigh0, D_IN / 4);
    sage_gemm_kernel<D_IN, true><<<dim3(D_H / 64, N1 / 128), 256>>>(
        x, p_neigh0, Ws0, Wn0, b0, p_h1);

    // Layer 1 (h1 fits in L2 -> gather is cheap)
    gather_mean_kernel<F1><<<N2, 128>>>(p_h1, nbr1, p_neigh1, D_H / 4);
    sage_gemm_kernel<D_H, true><<<dim3(D_H / 64, N2 / 128), 256>>>(
        p_h1, p_neigh1, Ws1, Wn1, b1, p_h2);

    // Layer 2 (output)
    gather_mean_kernel<F2><<<N3, 128>>>(p_h2, nbr2, p_neigh2, D_H / 4);
    sage_out_kernel<<<N3, D_OUT * 32>>>(p_h2, p_neigh2, Ws2, Wn2, b2, out);
}

// round 14
// speedup vs baseline: 1.5219x; 1.5219x over previous
#include <cuda_runtime.h>
#include <cuda_bf16.h>
#include <cstdint>

// ---------------------------------------------------------------------------
// Problem constants
// ---------------------------------------------------------------------------
#define N0 256000
#define N1 25600
#define N2 2560
#define N3 512
#define D_IN 1024
#define D_H 256
#define D_OUT 19
#define F0 10
#define F1 10
#define F2 5

// ---------------------------------------------------------------------------
// Scratch (__device__ globals: allocation-free, graph-capturable)
// ---------------------------------------------------------------------------
__device__ float g_h1[N1 * D_H];
__device__ float g_neigh1[N2 * D_H];
__device__ float g_h2[N2 * D_H];
__device__ float g_neigh2[N3 * D_H];
// Layer-0 GEMM operands, all bf16 hi/lo split:
__device__ __nv_bfloat16 g_xh[N1 * D_IN];    // self rows of x, hi
__device__ __nv_bfloat16 g_xl[N1 * D_IN];    // self rows of x, lo
__device__ __nv_bfloat16 g_nbh[N1 * D_IN];   // gathered-mean, hi
__device__ __nv_bfloat16 g_nbl[N1 * D_IN];   // gathered-mean, lo
// Pre-transposed weights [N=256][K=1024], K-major, hi/lo:
__device__ __nv_bfloat16 g_WsT_hi[D_H * D_IN];
__device__ __nv_bfloat16 g_WsT_lo[D_H * D_IN];
__device__ __nv_bfloat16 g_WnT_hi[D_H * D_IN];
__device__ __nv_bfloat16 g_WnT_lo[D_H * D_IN];

// ---------------------------------------------------------------------------
// mma.sync m16n8k16 bf16 (row.col), f32 accum — plain PTX, works on sm_103.
// ---------------------------------------------------------------------------
__device__ __forceinline__ void mma16816(float* c, const uint32_t* a,
                                         const uint32_t* b) {
    asm volatile(
        "mma.sync.aligned.m16n8k16.row.col.f32.bf16.bf16.f32 "
        "{%0,%1,%2,%3}, {%4,%5,%6,%7}, {%8,%9}, {%0,%1,%2,%3};"
        : "+f"(c[0]), "+f"(c[1]), "+f"(c[2]), "+f"(c[3])
        : "r"(a[0]), "r"(a[1]), "r"(a[2]), "r"(a[3]), "r"(b[0]), "r"(b[1]));
}

__device__ __forceinline__ uint32_t pack_bf2(__nv_bfloat16 lo, __nv_bfloat16 hi) {
    __nv_bfloat162 v(lo, hi);
    return *reinterpret_cast<uint32_t*>(&v);
}

// ---------------------------------------------------------------------------
// Weight transpose + bf16 hi/lo split: W[K][256] -> T[256][K]
// ---------------------------------------------------------------------------
__global__ void convert_weights_kernel(const float* __restrict__ W,
                                       __nv_bfloat16* __restrict__ T_hi,
                                       __nv_bfloat16* __restrict__ T_lo,
                                       int Kd) {
    int idx = blockIdx.x * blockDim.x + threadIdx.x;
    if (idx < Kd * D_H) {
        int k = idx / D_H, n = idx % D_H;
        float w = W[idx];
        __nv_bfloat16 h = __float2bfloat16(w);
        T_hi[n * Kd + k] = h;
        T_lo[n * Kd + k] = __float2bfloat16(w - __bfloat162float(h));
    }
}

// ---------------------------------------------------------------------------
// fp32 rows -> bf16 hi/lo (same layout), 4 elems per thread
// ---------------------------------------------------------------------------
__global__ void split_rows_kernel(const float* __restrict__ x,
                                  __nv_bfloat16* __restrict__ h,
                                  __nv_bfloat16* __restrict__ l,
                                  long n4) {
    long i = (long)blockIdx.x * blockDim.x + threadIdx.x;
    if (i < n4) {
        float4 v = reinterpret_cast<const float4*>(x)[i];
        __nv_bfloat16 hx = __float2bfloat16(v.x), hy = __float2bfloat16(v.y);
        __nv_bfloat16 hz = __float2bfloat16(v.z), hw = __float2bfloat16(v.w);
        uint2 ph = make_uint2(pack_bf2(hx, hy), pack_bf2(hz, hw));
        uint2 pl = make_uint2(
            pack_bf2(__float2bfloat16(v.x - __bfloat162float(hx)),
                     __float2bfloat16(v.y - __bfloat162float(hy))),
            pack_bf2(__float2bfloat16(v.z - __bfloat162float(hz)),
                     __float2bfloat16(v.w - __bfloat162float(hw))));
        reinterpret_cast<uint2*>(h)[i] = ph;
        reinterpret_cast<uint2*>(l)[i] = pl;
    }
}

// ---------------------------------------------------------------------------
// Gather + mean -> bf16 hi/lo output (layer 0 only)
// ---------------------------------------------------------------------------
template <int FANOUT>
__global__ void gather_mean_split_kernel(const float* __restrict__ src,
                                         const int* __restrict__ nbr,
                                         __nv_bfloat16* __restrict__ dh,
                                         __nv_bfloat16* __restrict__ dl,
                                         int d4) {
    const int i = blockIdx.x;
    const float4* __restrict__ s4 = reinterpret_cast<const float4*>(src);
    constexpr float inv = 1.0f / (float)FANOUT;
    const float4* base[FANOUT];
#pragma unroll
    for (int j = 0; j < FANOUT; ++j) {
        int n = __ldg(&nbr[i * FANOUT + j]);
        base[j] = s4 + (long)n * d4;
    }
    for (int c = threadIdx.x; c < d4; c += blockDim.x) {
        float ax = 0.f, ay = 0.f, az = 0.f, aw = 0.f;
#pragma unroll
        for (int j = 0; j < FANOUT; ++j) {
            float4 v = __ldg(&base[j][c]);
            ax += v.x; ay += v.y; az += v.z; aw += v.w;
        }
        ax *= inv; ay *= inv; az *= inv; aw *= inv;
        __nv_bfloat16 hx = __float2bfloat16(ax), hy = __float2bfloat16(ay);
        __nv_bfloat16 hz = __float2bfloat16(az), hw = __float2bfloat16(aw);
        long o = (long)i * d4 + c;
        reinterpret_cast<uint2*>(dh)[o] =
            make_uint2(pack_bf2(hx, hy), pack_bf2(hz, hw));
        reinterpret_cast<uint2*>(dl)[o] = make_uint2(
            pack_bf2(__float2bfloat16(ax - __bfloat162float(hx)),
                     __float2bfloat16(ay - __bfloat162float(hy))),
            pack_bf2(__float2bfloat16(az - __bfloat162float(hz)),
                     __float2bfloat16(aw - __bfloat162float(hw))));
    }
}

// ---------------------------------------------------------------------------
// Plain fp32 gather (layers 1-2)
// ---------------------------------------------------------------------------
template <int FANOUT>
__global__ void gather_mean_kernel(const float* __restrict__ src,
                                   const int* __restrict__ nbr,
                                   float* __restrict__ dst, int d4) {
    const int i = blockIdx.x;
    const float4* __restrict__ s4 = reinterpret_cast<const float4*>(src);
    float4* __restrict__ d4p = reinterpret_cast<float4*>(dst);
    constexpr float inv = 1.0f / (float)FANOUT;
    const float4* base[FANOUT];
#pragma unroll
    for (int j = 0; j < FANOUT; ++j) {
        int n = __ldg(&nbr[i * FANOUT + j]);
        base[j] = s4 + (long)n * d4;
    }
    for (int c = threadIdx.x; c < d4; c += blockDim.x) {
        float ax = 0.f, ay = 0.f, az = 0.f, aw = 0.f;
#pragma unroll
        for (int j = 0; j < FANOUT; ++j) {
            float4 v = __ldg(&base[j][c]);
            ax += v.x; ay += v.y; az += v.z; aw += v.w;
        }
        d4p[(long)i * d4 + c] = make_float4(ax * inv, ay * inv, az * inv, aw * inv);
    }
}

// ---------------------------------------------------------------------------
// Layer-0 GEMM via mma.sync bf16 3-way split.
//   C[m][n] = relu( Aself@Ws + Aneigh@Wn + b ),  M=25600, N=256, K=1024
// BM=128, BN=64, BK=32; 256 threads = 8 warps (4m x 2n), warp tile 32x32.
// Smem rows padded to 40 bf16 (80B) -> conflict-free fragment loads
// (bank = 20*g + tg mod 32 covers all 32 banks).
// ---------------------------------------------------------------------------
#define S_STAGE 30720                     // bytes per stage
#define S_AH 0                            // 128*40*2 = 10240
#define S_AL 10240
#define S_BH 20480                        // 64*40*2 = 5120
#define S_BL 25600
#define G0_SMEM (2 * S_STAGE)             // 61440

template <int K>
__global__ __launch_bounds__(256) void mma_gemm0_kernel(
    const __nv_bfloat16* __restrict__ Ash, const __nv_bfloat16* __restrict__ Asl,
    const __nv_bfloat16* __restrict__ Anh, const __nv_bfloat16* __restrict__ Anl,
    const __nv_bfloat16* __restrict__ Wsh, const __nv_bfloat16* __restrict__ Wsl,
    const __nv_bfloat16* __restrict__ Wnh, const __nv_bfloat16* __restrict__ Wnl,
    const float* __restrict__ bias, float* __restrict__ C) {
    constexpr int TILES = K / 32;         // per pass
    constexpr int TOTAL = 2 * TILES;
    extern __shared__ char sm[];

    const int tid = threadIdx.x;
    const int wid = tid >> 5;
    const int lane = tid & 31;
    const int g = lane >> 2;              // group 0..7
    const int tg = lane & 3;              // thread-in-group 0..3
    const int wm = wid >> 1;              // 0..3
    const int wn = wid & 1;               // 0..1
    const int m0 = blockIdx.y * 128;
    const int n0 = blockIdx.x * 64;

    // global load coords (fixed)
    const int ar0 = (tid + 0)   >> 2, ak0 = ((tid + 0)   & 3) * 8;
    const int ar1 = (tid + 256) >> 2, ak1 = ((tid + 256) & 3) * 8;
    const int br  = tid >> 2,         bk  = (tid & 3) * 8;

    float acc[2][4][4];
#pragma unroll
    for (int i = 0; i < 2; ++i)
#pragma unroll
        for (int j = 0; j < 4; ++j)
#pragma unroll
            for (int q = 0; q < 4; ++q) acc[i][j][q] = 0.f;

    uint4 pA[4], pB[2];                   // prefetch regs

    auto sts_tile = [&](int stage) {
        char* s = sm + stage * S_STAGE;
        *reinterpret_cast<uint4*>(s + S_AH + (ar0 * 40 + ak0) * 2) = pA[0];
        *reinterpret_cast<uint4*>(s + S_AH + (ar1 * 40 + ak1) * 2) = pA[1];
        *reinterpret_cast<uint4*>(s + S_AL + (ar0 * 40 + ak0) * 2) = pA[2];
        *reinterpret_cast<uint4*>(s + S_AL + (ar1 * 40 + ak1) * 2) = pA[3];
        *reinterpret_cast<uint4*>(s + S_BH + (br * 40 + bk) * 2)   = pB[0];
        *reinterpret_cast<uint4*>(s + S_BL + (br * 40 + bk) * 2)   = pB[1];
    };
    auto ldg_tile = [&](int tt) {
        const int pass = tt / TILES;
        const int k0 = (tt % TILES) * 32;
        const __nv_bfloat16* __restrict__ Ah = pass ? Anh : Ash;
        const __nv_bfloat16* __restrict__ Al = pass ? Anl : Asl;
        const __nv_bfloat16* __restrict__ Bh = pass ? Wnh : Wsh;
        const __nv_bfloat16* __restrict__ Bl = pass ? Wnl : Wsl;
        pA[0] = *reinterpret_cast<const uint4*>(&Ah[(long)(m0 + ar0) * K + k0 + ak0]);
        pA[1] = *reinterpret_cast<const uint4*>(&Ah[(long)(m0 + ar1) * K + k0 + ak1]);
        pA[2] = *reinterpret_cast<const uint4*>(&Al[(long)(m0 + ar0) * K + k0 + ak0]);
        pA[3] = *reinterpret_cast<const uint4*>(&Al[(long)(m0 + ar1) * K + k0 + ak1]);
        pB[0] = *reinterpret_cast<const uint4*>(&Bh[(long)(n0 + br) * K + k0 + bk]);
        pB[1] = *reinterpret_cast<const uint4*>(&Bl[(long)(n0 + br) * K + k0 + bk]);
    };

    ldg_tile(0);
    sts_tile(0);
    __syncthreads();

#pragma unroll 1
    for (int t = 0; t < TOTAL; ++t) {
        const int cur = t & 1;
        const bool has_next = (t + 1 < TOTAL);
        if (has_next) ldg_tile(t + 1);

        const char* s = sm + cur * S_STAGE;
#pragma unroll
        for (int ks = 0; ks < 2; ++ks) {
            const int kb = ks * 16 + tg * 2;      // fragment k offset
            uint32_t ah[2][4], al[2][4], bh[4][2], bl[4][2];
#pragma unroll
            for (int mt = 0; mt < 2; ++mt) {
                int r0 = wm * 32 + mt * 16 + g, r1 = r0 + 8;
                ah[mt][0] = *reinterpret_cast<const uint32_t*>(s + S_AH + (r0 * 40 + kb) * 2);
                ah[mt][1] = *reinterpret_cast<const uint32_t*>(s + S_AH + (r1 * 40 + kb) * 2);
                ah[mt][2] = *reinterpret_cast<const uint32_t*>(s + S_AH + (r0 * 40 + kb + 8) * 2);
                ah[mt][3] = *reinterpret_cast<const uint32_t*>(s + S_AH + (r1 * 40 + kb + 8) * 2);
                al[mt][0] = *reinterpret_cast<const uint32_t*>(s + S_AL + (r0 * 40 + kb) * 2);
                al[mt][1] = *reinterpret_cast<const uint32_t*>(s + S_AL + (r1 * 40 + kb) * 2);
                al[mt][2] = *reinterpret_cast<const uint32_t*>(s + S_AL + (r0 * 40 + kb + 8) * 2);
                al[mt][3] = *reinterpret_cast<const uint32_t*>(s + S_AL + (r1 * 40 + kb + 8) * 2);
            }
#pragma unroll
            for (int nt = 0; nt < 4; ++nt) {
                int n = wn * 32 + nt * 8 + g;
                bh[nt][0] = *reinterpret_cast<const uint32_t*>(s + S_BH + (n * 40 + kb) * 2);
                bh[nt][1] = *reinterpret_cast<const uint32_t*>(s + S_BH + (n * 40 + kb + 8) * 2);
                bl[nt][0] = *reinterpret_cast<const uint32_t*>(s + S_BL + (n * 40 + kb) * 2);
                bl[nt][1] = *reinterpret_cast<const uint32_t*>(s + S_BL + (n * 40 + kb + 8) * 2);
            }
#pragma unroll
            for (int mt = 0; mt < 2; ++mt)
#pragma unroll
                for (int nt = 0; nt < 4; ++nt) mma16816(acc[mt][nt], ah[mt], bh[nt]);
#pragma unroll
            for (int mt = 0; mt < 2; ++mt)
#pragma unroll
                for (int nt = 0; nt < 4; ++nt) mma16816(acc[mt][nt], al[mt], bh[nt]);
#pragma unroll
            for (int mt = 0; mt < 2; ++mt)
#pragma unroll
                for (int nt = 0; nt < 4; ++nt) mma16816(acc[mt][nt], ah[mt], bl[nt]);
        }

        if (has_next) sts_tile(cur ^ 1);
        __syncthreads();
    }

    // Epilogue: bias + ReLU, float2 stores from C fragments
#pragma unroll
    for (int mt = 0; mt < 2; ++mt) {
#pragma unroll
        for (int nt = 0; nt < 4; ++nt) {
            int row0 = m0 + wm * 32 + mt * 16 + g;
            int col = n0 + wn * 32 + nt * 8 + tg * 2;
            float bx = __ldg(&bias[col]), by = __ldg(&bias[col + 1]);
            float2 v0 = make_float2(fmaxf(acc[mt][nt][0] + bx, 0.f),
                                    fmaxf(acc[mt][nt][1] + by, 0.f));
            float2 v1 = make_float2(fmaxf(acc[mt][nt][2] + bx, 0.f),
                                    fmaxf(acc[mt][nt][3] + by, 0.f));
            *reinterpret_cast<float2*>(&C[(long)row0 * 256 + col]) = v0;
            *reinterpret_cast<float2*>(&C[(long)(row0 + 8) * 256 + col]) = v1;
        }
    }
}

// ---------------------------------------------------------------------------
// Layer-1 fused dual GEMM (fp32 FFMA, software-pipelined) — proven
// ---------------------------------------------------------------------------
template <int K, bool RELU>
__global__ __launch_bounds__(256) void sage_gemm_kernel(
    const float* __restrict__ Aself, const float* __restrict__ Aneigh,
    const float* __restrict__ Ws, const float* __restrict__ Wn,
    const float* __restrict__ bias, float* __restrict__ C) {
    constexpr int BM = 128, BN = 64, BK = 16, N = 256;
    constexpr int TILES = K / BK;
    constexpr int TOTAL = 2 * TILES;
    __shared__ float As[2][BK][BM + 4];
    __shared__ float Bs[2][BK][BN];

    const int tid = threadIdx.x;
    const int tx = tid & 15;
    const int ty = tid >> 4;
    const int m0 = blockIdx.y * BM;
    const int n0 = blockIdx.x * BN;

    const int am0 = (tid + 0)   >> 2;
    const int ak0 = ((tid + 0)  & 3) * 4;
    const int am1 = (tid + 256) >> 2;
    const int ak1 = ((tid + 256)& 3) * 4;
    const int bk  = tid >> 4;
    const int bn  = (tid & 15) * 4;

    float acc[8][4];
#pragma unroll
    for (int i = 0; i < 8; ++i)
#pragma unroll
        for (int j = 0; j < 4; ++j) acc[i][j] = 0.f;

    float4 pa0, pa1, pb;
    {
        pa0 = *reinterpret_cast<const float4*>(&Aself[(long)(m0 + am0) * K + ak0]);
        pa1 = *reinterpret_cast<const float4*>(&Aself[(long)(m0 + am1) * K + ak1]);
        pb  = *reinterpret_cast<const float4*>(&Ws[(long)bk * N + n0 + bn]);
        As[0][ak0 + 0][am0] = pa0.x; As[0][ak0 + 1][am0] = pa0.y;
        As[0][ak0 + 2][am0] = pa0.z; As[0][ak0 + 3][am0] = pa0.w;
        As[0][ak1 + 0][am1] = pa1.x; As[0][ak1 + 1][am1] = pa1.y;
        As[0][ak1 + 2][am1] = pa1.z; As[0][ak1 + 3][am1] = pa1.w;
        *reinterpret_cast<float4*>(&Bs[0][bk][bn]) = pb;
    }
    __syncthreads();

#pragma unroll 1
    for (int t = 0; t < TOTAL; ++t) {
        const int cur = t & 1;
        const bool has_next = (t + 1 < TOTAL);
        if (has_next) {
            const int tn = t + 1;
            const float* __restrict__ A = (tn < TILES) ? Aself : Aneigh;
            const float* __restrict__ B = (tn < TILES) ? Ws : Wn;
            const int k0 = (tn < TILES ? tn : tn - TILES) * BK;
            pa0 = *reinterpret_cast<const float4*>(&A[(long)(m0 + am0) * K + k0 + ak0]);
            pa1 = *reinterpret_cast<const float4*>(&A[(long)(m0 + am1) * K + k0 + ak1]);
            pb  = *reinterpret_cast<const float4*>(&B[(long)(k0 + bk) * N + n0 + bn]);
        }
#pragma unroll
        for (int kk = 0; kk < BK; ++kk) {
            float4 a0 = *reinterpret_cast<const float4*>(&As[cur][kk][ty * 8 + 0]);
            float4 a1 = *reinterpret_cast<const float4*>(&As[cur][kk][ty * 8 + 4]);
            float4 bv = *reinterpret_cast<const float4*>(&Bs[cur][kk][tx * 4]);
            float a[8] = {a0.x, a0.y, a0.z, a0.w, a1.x, a1.y, a1.z, a1.w};
            float b4[4] = {bv.x, bv.y, bv.z, bv.w};
#pragma unroll
            for (int i = 0; i < 8; ++i)
#pragma unroll
                for (int j = 0; j < 4; ++j) acc[i][j] += a[i] * b4[j];
        }
        if (has_next) {
            const int nxt = cur ^ 1;
            As[nxt][ak0 + 0][am0] = pa0.x; As[nxt][ak0 + 1][am0] = pa0.y;
            As[nxt][ak0 + 2][am0] = pa0.z; As[nxt][ak0 + 3][am0] = pa0.w;
            As[nxt][ak1 + 0][am1] = pa1.x; As[nxt][ak1 + 1][am1] = pa1.y;
            As[nxt][ak1 + 2][am1] = pa1.z; As[nxt][ak1 + 3][am1] = pa1.w;
            *reinterpret_cast<float4*>(&Bs[nxt][bk][bn]) = pb;
        }
        __syncthreads();
    }

#pragma unroll
    for (int i = 0; i < 8; ++i) {
        int m = m0 + ty * 8 + i;
        int n = n0 + tx * 4;
        float4 v;
        v.x = acc[i][0] + bias[n + 0];
        v.y = acc[i][1] + bias[n + 1];
        v.z = acc[i][2] + bias[n + 2];
        v.w = acc[i][3] + bias[n + 3];
        if (RELU) {
            v.x = fmaxf(v.x, 0.f); v.y = fmaxf(v.y, 0.f);
            v.z = fmaxf(v.z, 0.f); v.w = fmaxf(v.w, 0.f);
        }
        *reinterpret_cast<float4*>(&C[(long)m * N + n]) = v;
    }
}

// ---------------------------------------------------------------------------
// Output layer
// ---------------------------------------------------------------------------
__global__ void sage_out_kernel(const float* __restrict__ h,
                                const float* __restrict__ hn,
                                const float* __restrict__ Ws,
                                const float* __restrict__ Wn,
                                const float* __restrict__ bias,
                                float* __restrict__ out) {
    const int i = blockIdx.x;
    const int w = threadIdx.x >> 5;
    const int lane = threadIdx.x & 31;
    __shared__ float sh[D_H], sn[D_H];
    for (int k = threadIdx.x; k < D_H; k += blockDim.x) {
        sh[k] = h[(long)i * D_H + k];
        sn[k] = hn[(long)i * D_H + k];
    }
    __syncthreads();
    if (w < D_OUT) {
        float acc = 0.f;
        for (int k = lane; k < D_H; k += 32)
            acc += sh[k] * Ws[k * D_OUT + w] + sn[k] * Wn[k * D_OUT + w];
#pragma unroll
        for (int o = 16; o; o >>= 1) acc += __shfl_xor_sync(0xffffffffu, acc, o);
        if (lane == 0) out[i * D_OUT + w] = acc + bias[w];
    }
}

// ---------------------------------------------------------------------------
// Launch
// ---------------------------------------------------------------------------
extern "C" void kernel_launch(void* const* d_in, const int* in_sizes, int n_in,
                              void* d_out, int out_size) {
    const float* x     = (const float*)d_in[0];
    const int*   nbr0  = (const int*)  d_in[1];
    const int*   nbr1  = (const int*)  d_in[2];
    const int*   nbr2  = (const int*)  d_in[3];
    const float* Ws0   = (const float*)d_in[4];
    const float* Wn0   = (const float*)d_in[5];
    const float* b0    = (const float*)d_in[6];
    const float* Ws1   = (const float*)d_in[7];
    const float* Wn1   = (const float*)d_in[8];
    const float* b1    = (const float*)d_in[9];
    const float* Ws2   = (const float*)d_in[10];
    const float* Wn2   = (const float*)d_in[11];
    const float* b2    = (const float*)d_in[12];
    float* out = (float*)d_out;

    float *p_h1, *p_neigh1, *p_h2, *p_neigh2;
    __nv_bfloat16 *p_xh, *p_xl, *p_nbh, *p_nbl;
    __nv_bfloat16 *p_wsh, *p_wsl, *p_wnh, *p_wnl;
    cudaGetSymbolAddress((void**)&p_h1,     g_h1);
    cudaGetSymbolAddress((void**)&p_neigh1, g_neigh1);
    cudaGetSymbolAddress((void**)&p_h2,     g_h2);
    cudaGetSymbolAddress((void**)&p_neigh2, g_neigh2);
    cudaGetSymbolAddress((void**)&p_xh,  g_xh);
    cudaGetSymbolAddress((void**)&p_xl,  g_xl);
    cudaGetSymbolAddress((void**)&p_nbh, g_nbh);
    cudaGetSymbolAddress((void**)&p_nbl, g_nbl);
    cudaGetSymbolAddress((void**)&p_wsh, g_WsT_hi);
    cudaGetSymbolAddress((void**)&p_wsl, g_WsT_lo);
    cudaGetSymbolAddress((void**)&p_wnh, g_WnT_hi);
    cudaGetSymbolAddress((void**)&p_wnl, g_WnT_lo);

    cudaFuncSetAttribute(mma_gemm0_kernel<D_IN>,
                         cudaFuncAttributeMaxDynamicSharedMemorySize, G0_SMEM);

    // Precompute (deterministic each call)
    convert_weights_kernel<<<(D_IN * D_H + 255) / 256, 256>>>(Ws0, p_wsh, p_wsl, D_IN);
    convert_weights_kernel<<<(D_IN * D_H + 255) / 256, 256>>>(Wn0, p_wnh, p_wnl, D_IN);
    {
        long n4 = (long)N1 * D_IN / 4;
        split_rows_kernel<<<(int)((n4 + 255) / 256), 256>>>(x, p_xh, p_xl, n4);
    }

    // Layer 0: gather(split) -> mma GEMM
    gather_mean_split_kernel<F0><<<N1, 256>>>(x, nbr0, p_nbh, p_nbl, D_IN / 4);
    mma_gemm0_kernel<D_IN><<<dim3(256 / 64, N1 / 128), 256, G0_SMEM>>>(
        p_xh, p_xl, p_nbh, p_nbl, p_wsh, p_wsl, p_wnh, p_wnl, b0, p_h1);

    // Layer 1 (FFMA, proven)
    gather_mean_kernel<F1><<<N2, 128>>>(p_h1, nbr1, p_neigh1, D_H / 4);
    sage_gemm_kernel<D_H, true><<<dim3(D_H / 64, N2 / 128), 256>>>(
        p_h1, p_neigh1, Ws1, Wn1, b1, p_h2);

    // Layer 2 (output)
    gather_mean_kernel<F2><<<N3, 128>>>(p_h2, nbr2, p_neigh2, D_H / 4);
    sage_out_kernel<<<N3, D_OUT * 32>>>(p_h2, p_neigh2, Ws2, Wn2, b2, out);
}